// round 11
// baseline (speedup 1.0000x reference)
#include <cuda_runtime.h>
#include <math.h>

// Problem constants
#define B_   64
#define T_   4096
#define D_   512
#define NSEG 32                          // segments per batch
#define SEG_ROWS (T_ / NSEG)             // 128 rows per segment
#define NWARP 8
#define THREADS 256
#define ROWS_PER_WARP (SEG_ROWS / NWARP) // 16
#define CHUNKS (ROWS_PER_WARP / 2)       // 8 chunks of 2 rows, double-buffered

typedef unsigned long long u64;

// Per-(batch,segment) partial online-softmax state + completion counters.
__device__ float g_part_m[B_ * NSEG];
__device__ float g_part_l[B_ * NSEG];
__device__ float g_part_acc[B_ * NSEG * D_];
__device__ int   g_cnt[B_];              // zero-init; self-resetting each launch

__device__ __forceinline__ float neg_inf() { return __int_as_float(0xff800000); }

// ---- packed f32x2 helpers (FFMA2: PTX-only, halves fma-pipe issue) ----------
__device__ __forceinline__ u64 pack2(float lo, float hi) {
    u64 r; asm("mov.b64 %0,{%1,%2};" : "=l"(r) : "f"(lo), "f"(hi)); return r;
}
__device__ __forceinline__ void unpack2(u64 v, float& lo, float& hi) {
    asm("mov.b64 {%0,%1},%2;" : "=f"(lo), "=f"(hi) : "l"(v));
}
__device__ __forceinline__ u64 fma2(u64 a, u64 b, u64 c) {
    u64 d; asm("fma.rn.f32x2 %0,%1,%2,%3;" : "=l"(d) : "l"(a), "l"(b), "l"(c)); return d;
}
__device__ __forceinline__ u64 mul2(u64 a, u64 b) {
    u64 d; asm("mul.rn.f32x2 %0,%1,%2;" : "=l"(d) : "l"(a), "l"(b)); return d;
}
__device__ __forceinline__ u64 add2(u64 a, u64 b) {
    u64 d; asm("add.rn.f32x2 %0,%1,%2;" : "=l"(d) : "l"(a), "l"(b)); return d;
}

// Load one 2-row chunk (8 LDG.128 per warp = 1KB in flight) into buf[2][8].
__device__ __forceinline__ void load_chunk(const float* __restrict__ xw,
                                           int chunk, int lane, u64 buf[2][8])
{
    const ulonglong2* p0 =
        reinterpret_cast<const ulonglong2*>(xw + (size_t)(chunk * 2    ) * D_);
    const ulonglong2* p1 =
        reinterpret_cast<const ulonglong2*>(xw + (size_t)(chunk * 2 + 1) * D_);
    #pragma unroll
    for (int k = 0; k < 4; k++) {
        ulonglong2 t0 = p0[lane + 32 * k];
        buf[0][2*k] = t0.x; buf[0][2*k+1] = t0.y;
    }
    #pragma unroll
    for (int k = 0; k < 4; k++) {
        ulonglong2 t1 = p1[lane + 32 * k];
        buf[1][2*k] = t1.x; buf[1][2*k+1] = t1.y;
    }
}

// -----------------------------------------------------------------------------
// Single fused kernel, R6 config (256 threads, 2 CTAs/SM) with a software-
// pipelined mainloop: 2-row chunks, double-buffered — chunk c+1's loads are
// issued BEFORE chunk c's compute, so the shuffle/exp/accumulate tail always
// executes with 1KB/warp of loads in flight (continuous load issue, vs the
// batch-then-drain pattern that capped R6/R8 at ~79% DRAM).
// -----------------------------------------------------------------------------
__global__ __launch_bounds__(THREADS, 2)
void attn_fused(const float* __restrict__ x,
                const float* __restrict__ v,
                float* __restrict__ ctx,     // d_out          [B*D]
                float* __restrict__ wts)     // d_out + B*D    [B*T]
{
    __shared__ float s_m[NWARP], s_l[NWARP];
    __shared__ u64   s_acc[NWARP * 256];     // 16KB cross-warp reduce buffer
    __shared__ float s_scale[NSEG];          // merge-phase segment scales
    __shared__ int   s_last;

    const int tid  = threadIdx.x;
    const int warp = tid >> 5;
    const int lane = tid & 31;
    const int b    = blockIdx.x / NSEG;
    const int s    = blockIdx.x % NSEG;
    const int t0   = s * SEG_ROWS;

    // Warp-blocked rows: warp w owns rows [w*16, w*16+16) of the segment.
    const float* xw = x + ((size_t)b * T_ + t0 + warp * ROWS_PER_WARP) * D_;
    float* ew = wts + (size_t)b * T_ + t0 + warp * ROWS_PER_WARP;

    // v for this lane's 128 columns, packed as 8 f32x2 (loop-invariant)
    u64 vw[8];
    {
        const ulonglong2* v2 = reinterpret_cast<const ulonglong2*>(v);
        #pragma unroll
        for (int k = 0; k < 4; k++) {
            ulonglong2 t = v2[lane + 32 * k];
            vw[2*k] = t.x; vw[2*k+1] = t.y;
        }
    }

    u64 acc[8];
    #pragma unroll
    for (int i = 0; i < 8; i++) acc[i] = 0ull;   // packed {0.f, 0.f}
    float m = neg_inf();
    float l = 0.f;

    // ---- pipelined mainloop -------------------------------------------------
    u64 buf[2][2][8];                     // [stage][row][8]
    load_chunk(xw, 0, lane, buf[0]);

    #pragma unroll 2
    for (int c = 0; c < CHUNKS; c++) {
        const int st = c & 1;             // static under unroll 2
        if (c + 1 < CHUNKS)
            load_chunk(xw, c + 1, lane, buf[st ^ 1]);   // overlap with compute

        u64 (&xd)[2][8] = buf[st];

        // Two independent dot products (packed FMA)
        u64 ea2 = 0ull, eb2 = 0ull;
        #pragma unroll
        for (int i = 0; i < 8; i++) {
            ea2 = fma2(xd[0][i], vw[i], ea2);
            eb2 = fma2(xd[1][i], vw[i], eb2);
        }
        float al, ah, bl, bh;
        unpack2(ea2, al, ah); unpack2(eb2, bl, bh);
        float ea = al + ah, eb = bl + bh;
        #pragma unroll
        for (int o = 16; o; o >>= 1) {    // interleaved butterflies
            ea += __shfl_xor_sync(0xffffffffu, ea, o);
            eb += __shfl_xor_sync(0xffffffffu, eb, o);
        }

        // Raw energies straight to gmem (2 consecutive floats, STG.64)
        if (lane == 0) {
            float2 ev = make_float2(ea, eb);
            *reinterpret_cast<float2*>(ew + c * 2) = ev;
        }

        const float cmax = fmaxf(ea, eb);
        if (cmax > m) {                   // warp-uniform rescale path
            const float sc = __expf(m - cmax);   // 0 on first chunk (m=-inf)
            const u64 sc2 = pack2(sc, sc);
            l *= sc;
            #pragma unroll
            for (int i = 0; i < 8; i++) acc[i] = mul2(acc[i], sc2);
            m = cmax;
        }
        const float pa = __expf(ea - m);
        const float pb = __expf(eb - m);
        const u64 pa2 = pack2(pa, pa);
        const u64 pb2 = pack2(pb, pb);
        l += pa + pb;
        #pragma unroll
        for (int i = 0; i < 8; i++) {
            acc[i] = fma2(xd[0][i], pa2, acc[i]);
            acc[i] = fma2(xd[1][i], pb2, acc[i]);
        }
    }

    // ---- in-CTA merge of 8 warp partials ------------------------------------
    if (lane == 0) { s_m[warp] = m; s_l[warp] = l; }
    __syncthreads();

    float Mw = neg_inf();
    #pragma unroll
    for (int w = 0; w < NWARP; w++) Mw = fmaxf(Mw, s_m[w]);
    const float wsc = __expf(m - Mw);
    const u64 wsc2 = pack2(wsc, wsc);
    #pragma unroll
    for (int k = 0; k < 4; k++) {
        const int slot = 32 * k + lane;
        s_acc[warp * 256 + slot * 2    ] = mul2(acc[2*k],   wsc2);
        s_acc[warp * 256 + slot * 2 + 1] = mul2(acc[2*k+1], wsc2);
    }
    if (lane == 0) s_l[warp] = l * wsc;
    __syncthreads();

    const int bs = blockIdx.x;
    if (tid < 128) {
        u64 a0 = 0ull, a1 = 0ull;
        #pragma unroll
        for (int w = 0; w < NWARP; w++) {
            a0 = add2(a0, s_acc[w * 256 + tid * 2    ]);
            a1 = add2(a1, s_acc[w * 256 + tid * 2 + 1]);
        }
        ulonglong2 o2; o2.x = a0; o2.y = a1;
        reinterpret_cast<ulonglong2*>(g_part_acc)[(size_t)bs * 128 + tid] = o2;
    }
    if (tid == 0) {
        float L = 0.f;
        #pragma unroll
        for (int w = 0; w < NWARP; w++) L += s_l[w];
        g_part_m[bs] = Mw;
        g_part_l[bs] = L;
    }
    __syncthreads();

    // ---- last-CTA-per-batch detection (threadFenceReduction pattern) --------
    if (tid == 0) {
        __threadfence();
        const int old = atomicAdd(&g_cnt[b], 1);
        s_last = (old == NSEG - 1);
        if (s_last) atomicExch(&g_cnt[b], 0);   // reset for next graph replay
    }
    __syncthreads();
    if (!s_last) return;
    __threadfence();

    // ---- merge 32 segment partials for batch b ------------------------------
    if (tid < NSEG) s_scale[tid] = g_part_m[b * NSEG + tid];  // temp: m_i
    __syncthreads();
    float Mb = neg_inf();
    #pragma unroll
    for (int i = 0; i < NSEG; i++) Mb = fmaxf(Mb, s_scale[i]);
    float Lb = 0.f;
    #pragma unroll
    for (int i = 0; i < NSEG; i++)
        Lb += g_part_l[b * NSEG + i] * __expf(s_scale[i] - Mb);
    const float invL = 1.f / Lb;
    __syncthreads();
    if (tid < NSEG) s_scale[tid] = __expf(s_scale[tid] - Mb) * invL;
    __syncthreads();

    // context[b, :] — 2 columns per thread
    #pragma unroll
    for (int h = 0; h < 2; h++) {
        const int col = tid + h * THREADS;
        float a = 0.f;
        #pragma unroll
        for (int i = 0; i < NSEG; i++)
            a += g_part_acc[(size_t)(b * NSEG + i) * D_ + col] * s_scale[i];
        ctx[(size_t)b * D_ + col] = a;
    }

    // weights[b, :] = exp(e - Mb) * invL   (vectorized in-place)
    {
        float4* wb = reinterpret_cast<float4*>(wts + (size_t)b * T_);
        #pragma unroll
        for (int j = 0; j < 4; j++) {
            float4 w = wb[tid + j * THREADS];
            w.x = __expf(w.x - Mb) * invL;
            w.y = __expf(w.y - Mb) * invL;
            w.z = __expf(w.z - Mb) * invL;
            w.w = __expf(w.w - Mb) * invL;
            wb[tid + j * THREADS] = w;
        }
    }
}

// -----------------------------------------------------------------------------
extern "C" void kernel_launch(void* const* d_in, const int* in_sizes, int n_in,
                              void* d_out, int out_size)
{
    const float* x = (const float*)d_in[0];   // encoder_outputs [B,T,D]
    const float* v = (const float*)d_in[1];   // attn_weights_param [D,1]
    float* out = (float*)d_out;
    float* ctx = out;                 // [B*D]
    float* wts = out + B_ * D_;       // [B*T]

    attn_fused<<<B_ * NSEG, THREADS>>>(x, v, ctx, wts);
}